// round 14
// baseline (speedup 1.0000x reference)
#include <cuda_runtime.h>

// GSA_69063074119914 — scalar-channel spatial-reduction attention.
// ONE launch, self-sufficient CTAs. Grid (16,16): CTA = (8-row slice, batch),
// 256 threads, 2 CTAs/SM.
//   conv:  redundant per CTA, 1 cell/thread, ALL 16 LDG.128 prefetched
//   table: 16 local nodes; warp w owns keys [32w,32w+32); lane: node=lane&15,
//          key-half=lane>>4; shfl_xor(16) half-combine; 8-warp smem combine
//   eval:  exact-derivative cubic Hermite, 4 in-register queries/thread

#define NB     16
#define NSLICE 16
#define HW     16384
#define NT     256     // keys per batch
#define NPL    16      // local table nodes per CTA
#define LOG2E  1.4426950408889634f
#define LN2    0.6931471805599453f

__global__ void __launch_bounds__(256, 2) gsa_kernel(
        const float* __restrict__ x,
        const float* __restrict__ wq, const float* __restrict__ bq,
        const float* __restrict__ wk, const float* __restrict__ bk,
        const float* __restrict__ wv, const float* __restrict__ bv,
        const float* __restrict__ cw, const float* __restrict__ cb,
        float* __restrict__ out)
{
    __shared__ float  s_cw[64];
    __shared__ __align__(16) float2 s_kv[NT];    // (k*log2e, v)
    __shared__ float4 s_part[8][NPL];            // per-warp partial sums
    __shared__ float2 s_tab[NPL];                // (f, f' * hstep)
    __shared__ float  s_qmn[8], s_qmx[8], s_kmn[8], s_kmx[8];

    const int b    = blockIdx.y;
    const int r    = blockIdx.x;                 // 8-row slice
    const int t    = threadIdx.x;
    const int lane = t & 31;
    const int warp = t >> 5;

    const float wq0 = wq[0], bq0 = bq[0];
    const float wk0 = wk[0], bk0 = bk[0];
    const float wv0 = wv[0], bv0 = bv[0];
    const float cb0 = cb[0];
    if (t < 64) s_cw[t] = cw[t];

    const float* xb = x + (size_t)b * HW;

    // ===== queries: 4 per thread (rows [8r,8r+8), 32 threads/row) =====
    const size_t segoff = (size_t)(8 * r + (t >> 5)) * 128 + (size_t)(t & 31) * 4;
    const float4 xq = *(const float4*)(xb + segoff);
    float qv[4] = { fmaf(wq0, xq.x, bq0), fmaf(wq0, xq.y, bq0),
                    fmaf(wq0, xq.z, bq0), fmaf(wq0, xq.w, bq0) };

    // ===== conv: prefetch ALL 16 LDG.128 for cell (rr, oct) =====
    const int rr  = t >> 4;
    const int oct = t & 15;
    const float* cbase = xb + (size_t)rr * 1024 + oct * 8;
    float4 p0  = *(const float4*)(cbase + 0 * 128);
    float4 p1  = *(const float4*)(cbase + 0 * 128 + 4);
    float4 p2  = *(const float4*)(cbase + 1 * 128);
    float4 p3  = *(const float4*)(cbase + 1 * 128 + 4);
    float4 p4  = *(const float4*)(cbase + 2 * 128);
    float4 p5  = *(const float4*)(cbase + 2 * 128 + 4);
    float4 p6  = *(const float4*)(cbase + 3 * 128);
    float4 p7  = *(const float4*)(cbase + 3 * 128 + 4);
    float4 p8  = *(const float4*)(cbase + 4 * 128);
    float4 p9  = *(const float4*)(cbase + 4 * 128 + 4);
    float4 p10 = *(const float4*)(cbase + 5 * 128);
    float4 p11 = *(const float4*)(cbase + 5 * 128 + 4);
    float4 p12 = *(const float4*)(cbase + 6 * 128);
    float4 p13 = *(const float4*)(cbase + 6 * 128 + 4);
    float4 p14 = *(const float4*)(cbase + 7 * 128);
    float4 p15 = *(const float4*)(cbase + 7 * 128 + 4);

    // local q-range while loads fly
    float qmn = fminf(fminf(qv[0], qv[1]), fminf(qv[2], qv[3]));
    float qmx = fmaxf(fmaxf(qv[0], qv[1]), fmaxf(qv[2], qv[3]));
#pragma unroll
    for (int off = 16; off > 0; off >>= 1) {
        qmn = fminf(qmn, __shfl_xor_sync(0xffffffffu, qmn, off));
        qmx = fmaxf(qmx, __shfl_xor_sync(0xffffffffu, qmx, off));
    }
    if (lane == 0) { s_qmn[warp] = qmn; s_qmx[warp] = qmx; }
    __syncthreads();   // s_cw visible

    // conv FMAs, 4 independent accumulators
    float d0, d1, d2, d3;
    {
        const float* w = s_cw;
        d0 =       p0.x  * w[0];
        d0 = fmaf(p0.y,  w[1],  d0); d0 = fmaf(p0.z,  w[2],  d0);
        d0 = fmaf(p0.w,  w[3],  d0); d0 = fmaf(p1.x,  w[4],  d0);
        d0 = fmaf(p1.y,  w[5],  d0); d0 = fmaf(p1.z,  w[6],  d0);
        d0 = fmaf(p1.w,  w[7],  d0);
        d1 =       p2.x  * w[8];
        d1 = fmaf(p2.y,  w[9],  d1); d1 = fmaf(p2.z,  w[10], d1);
        d1 = fmaf(p2.w,  w[11], d1); d1 = fmaf(p3.x,  w[12], d1);
        d1 = fmaf(p3.y,  w[13], d1); d1 = fmaf(p3.z,  w[14], d1);
        d1 = fmaf(p3.w,  w[15], d1);
        d2 =       p4.x  * w[16];
        d2 = fmaf(p4.y,  w[17], d2); d2 = fmaf(p4.z,  w[18], d2);
        d2 = fmaf(p4.w,  w[19], d2); d2 = fmaf(p5.x,  w[20], d2);
        d2 = fmaf(p5.y,  w[21], d2); d2 = fmaf(p5.z,  w[22], d2);
        d2 = fmaf(p5.w,  w[23], d2);
        d3 =       p6.x  * w[24];
        d3 = fmaf(p6.y,  w[25], d3); d3 = fmaf(p6.z,  w[26], d3);
        d3 = fmaf(p6.w,  w[27], d3); d3 = fmaf(p7.x,  w[28], d3);
        d3 = fmaf(p7.y,  w[29], d3); d3 = fmaf(p7.z,  w[30], d3);
        d3 = fmaf(p7.w,  w[31], d3);

        d0 = fmaf(p8.x,  w[32], d0); d0 = fmaf(p8.y,  w[33], d0);
        d0 = fmaf(p8.z,  w[34], d0); d0 = fmaf(p8.w,  w[35], d0);
        d0 = fmaf(p9.x,  w[36], d0); d0 = fmaf(p9.y,  w[37], d0);
        d0 = fmaf(p9.z,  w[38], d0); d0 = fmaf(p9.w,  w[39], d0);
        d1 = fmaf(p10.x, w[40], d1); d1 = fmaf(p10.y, w[41], d1);
        d1 = fmaf(p10.z, w[42], d1); d1 = fmaf(p10.w, w[43], d1);
        d1 = fmaf(p11.x, w[44], d1); d1 = fmaf(p11.y, w[45], d1);
        d1 = fmaf(p11.z, w[46], d1); d1 = fmaf(p11.w, w[47], d1);
        d2 = fmaf(p12.x, w[48], d2); d2 = fmaf(p12.y, w[49], d2);
        d2 = fmaf(p12.z, w[50], d2); d2 = fmaf(p12.w, w[51], d2);
        d2 = fmaf(p13.x, w[52], d2); d2 = fmaf(p13.y, w[53], d2);
        d2 = fmaf(p13.z, w[54], d2); d2 = fmaf(p13.w, w[55], d2);
        d3 = fmaf(p14.x, w[56], d3); d3 = fmaf(p14.y, w[57], d3);
        d3 = fmaf(p14.z, w[58], d3); d3 = fmaf(p14.w, w[59], d3);
        d3 = fmaf(p15.x, w[60], d3); d3 = fmaf(p15.y, w[61], d3);
        d3 = fmaf(p15.z, w[62], d3); d3 = fmaf(p15.w, w[63], d3);
    }
    const float ds = (d0 + d1) + (d2 + d3) + cb0;
    const float k2 = fmaf(wk0, ds, bk0) * LOG2E;
    const float vv = fmaf(wv0, ds, bv0);
    s_kv[t] = make_float2(k2, vv);

    float kmn = k2, kmx = k2;
#pragma unroll
    for (int off = 16; off > 0; off >>= 1) {
        kmn = fminf(kmn, __shfl_xor_sync(0xffffffffu, kmn, off));
        kmx = fmaxf(kmx, __shfl_xor_sync(0xffffffffu, kmx, off));
    }
    if (lane == 0) { s_kmn[warp] = kmn; s_kmx[warp] = kmx; }
    __syncthreads();

    // ===== redundant final reductions in registers =====
    float qlo = s_qmn[0], qhi = s_qmx[0];
    kmn = s_kmn[0]; kmx = s_kmx[0];
#pragma unroll
    for (int w = 1; w < 8; ++w) {
        qlo = fminf(qlo, s_qmn[w]);
        qhi = fmaxf(qhi, s_qmx[w]);
        kmn = fminf(kmn, s_kmn[w]);
        kmx = fmaxf(kmx, s_kmx[w]);
    }
    const float range = qhi - qlo;
    const float hstep = range * (1.0f / (NPL - 1));
    const float scale = (range > 0.f) ? (NPL - 1) / range : 0.f;

    // ===== table: warp w keys [32w,32w+32); node=lane&15, half=lane>>4 =====
    {
        const int  node = lane & 15;
        const int  half = lane >> 4;
        const float qn = fmaf(hstep, (float)node, qlo);
        const float m2 = fmaxf(qn * kmx, qn * kmn);   // exact max exponent

        float S0a = 0.f, S1a = 0.f, S2a = 0.f, S3a = 0.f;
        float S0b = 0.f, S1b = 0.f, S2b = 0.f, S3b = 0.f;
        const float2* kvh = s_kv + warp * 32 + half * 16;
#pragma unroll
        for (int u = 0; u < 16; u += 2) {
            const float4 kk = *(const float4*)(kvh + u);   // 2 (k,v) pairs
            float e0, e1;
            const float x0 = fmaf(qn, kk.x, -m2);
            const float x1 = fmaf(qn, kk.z, -m2);
            asm("ex2.approx.f32 %0, %1;" : "=f"(e0) : "f"(x0));
            asm("ex2.approx.f32 %0, %1;" : "=f"(e1) : "f"(x1));
            const float ve0 = kk.y * e0;
            const float ve1 = kk.w * e1;
            S0a += e0;              S0b += e1;
            S1a += ve0;             S1b += ve1;
            S2a = fmaf(kk.x, e0,  S2a);  S2b = fmaf(kk.z, e1,  S2b);
            S3a = fmaf(kk.x, ve0, S3a);  S3b = fmaf(kk.z, ve1, S3b);
        }
        float P0 = S0a + S0b, P1 = S1a + S1b;
        float P2 = S2a + S2b, P3 = S3a + S3b;
        // combine the two key-halves (lanes n and n+16 hold the same node)
        P0 += __shfl_xor_sync(0xffffffffu, P0, 16);
        P1 += __shfl_xor_sync(0xffffffffu, P1, 16);
        P2 += __shfl_xor_sync(0xffffffffu, P2, 16);
        P3 += __shfl_xor_sync(0xffffffffu, P3, 16);
        if (half == 0) s_part[warp][node] = make_float4(P0, P1, P2, P3);
        __syncthreads();
        if (t < NPL) {   // 16 threads: sum the 8 warp partials for node t
            float4 a0 = s_part[0][t], a1 = s_part[1][t];
            float4 a2 = s_part[2][t], a3 = s_part[3][t];
            float4 a4 = s_part[4][t], a5 = s_part[5][t];
            float4 a6 = s_part[6][t], a7 = s_part[7][t];
            const float T0 = ((a0.x + a1.x) + (a2.x + a3.x)) +
                             ((a4.x + a5.x) + (a6.x + a7.x));
            const float T1 = ((a0.y + a1.y) + (a2.y + a3.y)) +
                             ((a4.y + a5.y) + (a6.y + a7.y));
            const float T2 = ((a0.z + a1.z) + (a2.z + a3.z)) +
                             ((a4.z + a5.z) + (a6.z + a7.z));
            const float T3 = ((a0.w + a1.w) + (a2.w + a3.w)) +
                             ((a4.w + a5.w) + (a6.w + a7.w));
            const float rcp = __frcp_rn(T0);
            const float f   = T1 * rcp;
            const float fp  = LN2 * rcp * fmaf(-f, T2, T3);
            const float qn2 = fmaf(hstep, (float)t, qlo);
            (void)qn2;
            s_tab[t] = make_float2(f, fp * hstep);        // u-space tangent
        }
    }
    __syncthreads();

    // ===== evaluate the 4 in-register queries =====
    float res[4];
#pragma unroll
    for (int e = 0; e < 4; ++e) {
        float tpos = (qv[e] - qlo) * scale;
        tpos = fminf(fmaxf(tpos, 0.f), (float)(NPL - 1));
        const int i = min((int)tpos, NPL - 2);
        const float u = tpos - (float)i;
        const float2 n0 = s_tab[i];
        const float2 n1 = s_tab[i + 1];
        const float d  = n1.x - n0.x;
        const float c2 = 3.f * d - 2.f * n0.y - n1.y;
        const float c3 = n0.y + n1.y - 2.f * d;
        res[e] = fmaf(u, fmaf(u, fmaf(u, c3, c2), n0.y), n0.x);
    }
    *(float4*)(out + (size_t)b * HW + segoff) =
        make_float4(res[0], res[1], res[2], res[3]);
}

extern "C" void kernel_launch(void* const* d_in, const int* in_sizes, int n_in,
                              void* d_out, int out_size)
{
    // metadata order: x, wq, bq, wk, bk, wv, bv, conv_w, conv_b
    const float* x  = (const float*)d_in[0];
    const float* wq = (const float*)d_in[1];
    const float* bq = (const float*)d_in[2];
    const float* wk = (const float*)d_in[3];
    const float* bk = (const float*)d_in[4];
    const float* wv = (const float*)d_in[5];
    const float* bv = (const float*)d_in[6];
    const float* cw = (const float*)d_in[7];
    const float* cb = (const float*)d_in[8];
    float* out = (float*)d_out;

    gsa_kernel<<<dim3(NSLICE, NB), 256>>>(x, wq, bq, wk, bk, wv, bv, cw, cb, out);
}

// round 15
// speedup vs baseline: 1.2664x; 1.2664x over previous
#include <cuda_runtime.h>

// GSA_69063074119914 — scalar-channel spatial-reduction attention.
// ONE launch, ONE balanced wave. Grid (8,16): CTA = (16-row slice, batch),
// 256 threads, 1 CTA/SM (128 CTAs < 148 SMs).
//   conv:  redundant per CTA, 1 cell/thread, ALL 16 LDG.128 prefetched
//   table: 16 local nodes; warp w owns keys [32w,32w+32); node=lane&15,
//          key-half=lane>>4; shfl_xor(16) half-combine; 16-thread final
//   eval:  exact-derivative cubic Hermite, 8 in-register queries/thread

#define NB     16
#define NSLICE 8
#define HW     16384
#define NT     256     // keys per batch
#define NPL    16      // local table nodes per CTA
#define LOG2E  1.4426950408889634f
#define LN2    0.6931471805599453f

__global__ void __launch_bounds__(256, 1) gsa_kernel(
        const float* __restrict__ x,
        const float* __restrict__ wq, const float* __restrict__ bq,
        const float* __restrict__ wk, const float* __restrict__ bk,
        const float* __restrict__ wv, const float* __restrict__ bv,
        const float* __restrict__ cw, const float* __restrict__ cb,
        float* __restrict__ out)
{
    __shared__ float  s_cw[64];
    __shared__ __align__(16) float2 s_kv[NT];    // (k*log2e, v)
    __shared__ float4 s_part[8][NPL];            // per-warp partial sums
    __shared__ float2 s_tab[NPL];                // (f, f' * hstep)
    __shared__ float  s_qmn[8], s_qmx[8], s_kmn[8], s_kmx[8];

    const int b    = blockIdx.y;
    const int r    = blockIdx.x;                 // 16-row slice
    const int t    = threadIdx.x;
    const int lane = t & 31;
    const int warp = t >> 5;

    const float wq0 = wq[0], bq0 = bq[0];
    const float wk0 = wk[0], bk0 = bk[0];
    const float wv0 = wv[0], bv0 = bv[0];
    const float cb0 = cb[0];
    if (t < 64) s_cw[t] = cw[t];

    const float* xb = x + (size_t)b * HW;

    // ===== queries: 8 per thread (two coalesced float4 chunks) =====
    const size_t qbase = (size_t)b * HW + (size_t)r * 2048 + (size_t)t * 4;
    const float4 xq0 = *(const float4*)(x + qbase);
    const float4 xq1 = *(const float4*)(x + qbase + 1024);

    // ===== conv: prefetch ALL 16 LDG.128 for cell (rr, oct) =====
    const int rr  = t >> 4;
    const int oct = t & 15;
    const float* cbase = xb + (size_t)rr * 1024 + oct * 8;
    float4 p0  = *(const float4*)(cbase + 0 * 128);
    float4 p1  = *(const float4*)(cbase + 0 * 128 + 4);
    float4 p2  = *(const float4*)(cbase + 1 * 128);
    float4 p3  = *(const float4*)(cbase + 1 * 128 + 4);
    float4 p4  = *(const float4*)(cbase + 2 * 128);
    float4 p5  = *(const float4*)(cbase + 2 * 128 + 4);
    float4 p6  = *(const float4*)(cbase + 3 * 128);
    float4 p7  = *(const float4*)(cbase + 3 * 128 + 4);
    float4 p8  = *(const float4*)(cbase + 4 * 128);
    float4 p9  = *(const float4*)(cbase + 4 * 128 + 4);
    float4 p10 = *(const float4*)(cbase + 5 * 128);
    float4 p11 = *(const float4*)(cbase + 5 * 128 + 4);
    float4 p12 = *(const float4*)(cbase + 6 * 128);
    float4 p13 = *(const float4*)(cbase + 6 * 128 + 4);
    float4 p14 = *(const float4*)(cbase + 7 * 128);
    float4 p15 = *(const float4*)(cbase + 7 * 128 + 4);

    // queries -> q-space, local q-range (while loads fly)
    float qv[8] = { fmaf(wq0, xq0.x, bq0), fmaf(wq0, xq0.y, bq0),
                    fmaf(wq0, xq0.z, bq0), fmaf(wq0, xq0.w, bq0),
                    fmaf(wq0, xq1.x, bq0), fmaf(wq0, xq1.y, bq0),
                    fmaf(wq0, xq1.z, bq0), fmaf(wq0, xq1.w, bq0) };
    float qmn = qv[0], qmx = qv[0];
#pragma unroll
    for (int e = 1; e < 8; ++e) {
        qmn = fminf(qmn, qv[e]);
        qmx = fmaxf(qmx, qv[e]);
    }
#pragma unroll
    for (int off = 16; off > 0; off >>= 1) {
        qmn = fminf(qmn, __shfl_xor_sync(0xffffffffu, qmn, off));
        qmx = fmaxf(qmx, __shfl_xor_sync(0xffffffffu, qmx, off));
    }
    if (lane == 0) { s_qmn[warp] = qmn; s_qmx[warp] = qmx; }
    __syncthreads();   // s_cw visible

    // conv FMAs, 4 independent accumulators
    float d0, d1, d2, d3;
    {
        const float* w = s_cw;
        d0 =       p0.x  * w[0];
        d0 = fmaf(p0.y,  w[1],  d0); d0 = fmaf(p0.z,  w[2],  d0);
        d0 = fmaf(p0.w,  w[3],  d0); d0 = fmaf(p1.x,  w[4],  d0);
        d0 = fmaf(p1.y,  w[5],  d0); d0 = fmaf(p1.z,  w[6],  d0);
        d0 = fmaf(p1.w,  w[7],  d0);
        d1 =       p2.x  * w[8];
        d1 = fmaf(p2.y,  w[9],  d1); d1 = fmaf(p2.z,  w[10], d1);
        d1 = fmaf(p2.w,  w[11], d1); d1 = fmaf(p3.x,  w[12], d1);
        d1 = fmaf(p3.y,  w[13], d1); d1 = fmaf(p3.z,  w[14], d1);
        d1 = fmaf(p3.w,  w[15], d1);
        d2 =       p4.x  * w[16];
        d2 = fmaf(p4.y,  w[17], d2); d2 = fmaf(p4.z,  w[18], d2);
        d2 = fmaf(p4.w,  w[19], d2); d2 = fmaf(p5.x,  w[20], d2);
        d2 = fmaf(p5.y,  w[21], d2); d2 = fmaf(p5.z,  w[22], d2);
        d2 = fmaf(p5.w,  w[23], d2);
        d3 =       p6.x  * w[24];
        d3 = fmaf(p6.y,  w[25], d3); d3 = fmaf(p6.z,  w[26], d3);
        d3 = fmaf(p6.w,  w[27], d3); d3 = fmaf(p7.x,  w[28], d3);
        d3 = fmaf(p7.y,  w[29], d3); d3 = fmaf(p7.z,  w[30], d3);
        d3 = fmaf(p7.w,  w[31], d3);

        d0 = fmaf(p8.x,  w[32], d0); d0 = fmaf(p8.y,  w[33], d0);
        d0 = fmaf(p8.z,  w[34], d0); d0 = fmaf(p8.w,  w[35], d0);
        d0 = fmaf(p9.x,  w[36], d0); d0 = fmaf(p9.y,  w[37], d0);
        d0 = fmaf(p9.z,  w[38], d0); d0 = fmaf(p9.w,  w[39], d0);
        d1 = fmaf(p10.x, w[40], d1); d1 = fmaf(p10.y, w[41], d1);
        d1 = fmaf(p10.z, w[42], d1); d1 = fmaf(p10.w, w[43], d1);
        d1 = fmaf(p11.x, w[44], d1); d1 = fmaf(p11.y, w[45], d1);
        d1 = fmaf(p11.z, w[46], d1); d1 = fmaf(p11.w, w[47], d1);
        d2 = fmaf(p12.x, w[48], d2); d2 = fmaf(p12.y, w[49], d2);
        d2 = fmaf(p12.z, w[50], d2); d2 = fmaf(p12.w, w[51], d2);
        d2 = fmaf(p13.x, w[52], d2); d2 = fmaf(p13.y, w[53], d2);
        d2 = fmaf(p13.z, w[54], d2); d2 = fmaf(p13.w, w[55], d2);
        d3 = fmaf(p14.x, w[56], d3); d3 = fmaf(p14.y, w[57], d3);
        d3 = fmaf(p14.z, w[58], d3); d3 = fmaf(p14.w, w[59], d3);
        d3 = fmaf(p15.x, w[60], d3); d3 = fmaf(p15.y, w[61], d3);
        d3 = fmaf(p15.z, w[62], d3); d3 = fmaf(p15.w, w[63], d3);
    }
    const float ds = (d0 + d1) + (d2 + d3) + cb0;
    const float k2 = fmaf(wk0, ds, bk0) * LOG2E;
    const float vv = fmaf(wv0, ds, bv0);
    s_kv[t] = make_float2(k2, vv);

    float kmn = k2, kmx = k2;
#pragma unroll
    for (int off = 16; off > 0; off >>= 1) {
        kmn = fminf(kmn, __shfl_xor_sync(0xffffffffu, kmn, off));
        kmx = fmaxf(kmx, __shfl_xor_sync(0xffffffffu, kmx, off));
    }
    if (lane == 0) { s_kmn[warp] = kmn; s_kmx[warp] = kmx; }
    __syncthreads();

    // ===== redundant final reductions in registers =====
    float qlo = s_qmn[0], qhi = s_qmx[0];
    kmn = s_kmn[0]; kmx = s_kmx[0];
#pragma unroll
    for (int w = 1; w < 8; ++w) {
        qlo = fminf(qlo, s_qmn[w]);
        qhi = fmaxf(qhi, s_qmx[w]);
        kmn = fminf(kmn, s_kmn[w]);
        kmx = fmaxf(kmx, s_kmx[w]);
    }
    const float range = qhi - qlo;
    const float hstep = range * (1.0f / (NPL - 1));
    const float scale = (range > 0.f) ? (NPL - 1) / range : 0.f;

    // ===== table: warp w keys [32w,32w+32); node=lane&15, half=lane>>4 =====
    {
        const int  node = lane & 15;
        const int  half = lane >> 4;
        const float qn = fmaf(hstep, (float)node, qlo);
        const float m2 = fmaxf(qn * kmx, qn * kmn);   // exact max exponent

        float S0a = 0.f, S1a = 0.f, S2a = 0.f, S3a = 0.f;
        float S0b = 0.f, S1b = 0.f, S2b = 0.f, S3b = 0.f;
        const float2* kvh = s_kv + warp * 32 + half * 16;
#pragma unroll
        for (int u = 0; u < 16; u += 2) {
            const float4 kk = *(const float4*)(kvh + u);   // 2 (k,v) pairs
            float e0, e1;
            const float x0 = fmaf(qn, kk.x, -m2);
            const float x1 = fmaf(qn, kk.z, -m2);
            asm("ex2.approx.f32 %0, %1;" : "=f"(e0) : "f"(x0));
            asm("ex2.approx.f32 %0, %1;" : "=f"(e1) : "f"(x1));
            const float ve0 = kk.y * e0;
            const float ve1 = kk.w * e1;
            S0a += e0;              S0b += e1;
            S1a += ve0;             S1b += ve1;
            S2a = fmaf(kk.x, e0,  S2a);  S2b = fmaf(kk.z, e1,  S2b);
            S3a = fmaf(kk.x, ve0, S3a);  S3b = fmaf(kk.z, ve1, S3b);
        }
        float P0 = S0a + S0b, P1 = S1a + S1b;
        float P2 = S2a + S2b, P3 = S3a + S3b;
        // combine key-halves: lanes n and n+16 hold the same node
        P0 += __shfl_xor_sync(0xffffffffu, P0, 16);
        P1 += __shfl_xor_sync(0xffffffffu, P1, 16);
        P2 += __shfl_xor_sync(0xffffffffu, P2, 16);
        P3 += __shfl_xor_sync(0xffffffffu, P3, 16);
        if (half == 0) s_part[warp][node] = make_float4(P0, P1, P2, P3);
        __syncthreads();
        if (t < NPL) {   // 16 threads: sum the 8 warp partials for node t
            float4 a0 = s_part[0][t], a1 = s_part[1][t];
            float4 a2 = s_part[2][t], a3 = s_part[3][t];
            float4 a4 = s_part[4][t], a5 = s_part[5][t];
            float4 a6 = s_part[6][t], a7 = s_part[7][t];
            const float T0 = ((a0.x + a1.x) + (a2.x + a3.x)) +
                             ((a4.x + a5.x) + (a6.x + a7.x));
            const float T1 = ((a0.y + a1.y) + (a2.y + a3.y)) +
                             ((a4.y + a5.y) + (a6.y + a7.y));
            const float T2 = ((a0.z + a1.z) + (a2.z + a3.z)) +
                             ((a4.z + a5.z) + (a6.z + a7.z));
            const float T3 = ((a0.w + a1.w) + (a2.w + a3.w)) +
                             ((a4.w + a5.w) + (a6.w + a7.w));
            const float rcp = __frcp_rn(T0);
            const float f   = T1 * rcp;
            const float fp  = LN2 * rcp * fmaf(-f, T2, T3);
            s_tab[t] = make_float2(f, fp * hstep);        // u-space tangent
        }
    }
    __syncthreads();

    // ===== evaluate the 8 in-register queries =====
    float res[8];
#pragma unroll
    for (int e = 0; e < 8; ++e) {
        float tpos = (qv[e] - qlo) * scale;
        tpos = fminf(fmaxf(tpos, 0.f), (float)(NPL - 1));
        const int i = min((int)tpos, NPL - 2);
        const float u = tpos - (float)i;
        const float2 n0 = s_tab[i];
        const float2 n1 = s_tab[i + 1];
        const float d  = n1.x - n0.x;
        const float c2 = 3.f * d - 2.f * n0.y - n1.y;
        const float c3 = n0.y + n1.y - 2.f * d;
        res[e] = fmaf(u, fmaf(u, fmaf(u, c3, c2), n0.y), n0.x);
    }
    *(float4*)(out + qbase)        = make_float4(res[0], res[1], res[2], res[3]);
    *(float4*)(out + qbase + 1024) = make_float4(res[4], res[5], res[6], res[7]);
}

extern "C" void kernel_launch(void* const* d_in, const int* in_sizes, int n_in,
                              void* d_out, int out_size)
{
    // metadata order: x, wq, bq, wk, bk, wv, bv, conv_w, conv_b
    const float* x  = (const float*)d_in[0];
    const float* wq = (const float*)d_in[1];
    const float* bq = (const float*)d_in[2];
    const float* wk = (const float*)d_in[3];
    const float* bk = (const float*)d_in[4];
    const float* wv = (const float*)d_in[5];
    const float* bv = (const float*)d_in[6];
    const float* cw = (const float*)d_in[7];
    const float* cb = (const float*)d_in[8];
    float* out = (float*)d_out;

    gsa_kernel<<<dim3(NSLICE, NB), 256>>>(x, wq, bq, wk, bk, wv, bv, cw, cb, out);
}